// round 13
// baseline (speedup 1.0000x reference)
#include <cuda_runtime.h>
#include <math.h>
#include <stdint.h>
#include <stddef.h>

// ---- problem constants ----
#define HD  256      // HIDDEN_DIM
#define ZD  64       // Z_DIM
#define BB  8        // batch
#define SL  2048     // SRC_LEN
#define QT  8        // queries per block in k_attn (2 CTAs/SM)
#define KC  512      // key chunk in k_attn
#define ES  8        // e-rows per pipeline stage
#define NST 32       // stages = (SL/KC) * (ZD/ES)
#define CAP 128      // per-row nonzero-attn list capacity
#define SKIP_T (-88.0f)
#define KZP 260      // padded smem row (floats) for prep M-part

typedef unsigned long long ull;

// ---- device scratch (no allocation allowed) ----
__device__ float g_venc[BB][HD];
__device__ float g_qenc[BB][HD];
__device__ float g_zsum[BB][ZD];
__device__ float g_M[ZD][ZD];
__device__ float g_wT[BB * ZD * SL]; // [b][d][key], w = (M z_k)/16
__device__ float g_c[BB][SL];        // c_k = (u_b . z_k)/16

// ---- packed fp32x2 helpers ----
__device__ __forceinline__ void fma2(ull& d, ull a, ull b) {
    asm("fma.rn.f32x2 %0, %1, %2, %0;" : "+l"(d) : "l"(a), "l"(b));
}
__device__ __forceinline__ ull dup2(float x) {
    ull r;
    asm("mov.b64 %0, {%1, %1};" : "=l"(r) : "f"(x));
    return r;
}
__device__ __forceinline__ void unpack2(float& lo, float& hi, ull v) {
    asm("mov.b64 {%0, %1}, %2;" : "=f"(lo), "=f"(hi) : "l"(v));
}

// ---- cp.async helpers ----
__device__ __forceinline__ void cp16(uint32_t saddr, const void* gaddr) {
    asm volatile("cp.async.cg.shared.global [%0], [%1], 16;"
                 :: "r"(saddr), "l"(gaddr));
}
__device__ __forceinline__ void cp_commit() {
    asm volatile("cp.async.commit_group;");
}
__device__ __forceinline__ void cp_wait0() {
    asm volatile("cp.async.wait_group 0;");
}

// ====== kernel 1 (fused): blocks 0..7 per-batch consts; 8..11 M tiles ======
__global__ void __launch_bounds__(1024, 1)
k_prep(const float* __restrict__ ehs,
       const float* __restrict__ z,
       const float* __restrict__ wq,
       const float* __restrict__ wk,
       const float* __restrict__ wv) {
    extern __shared__ char smraw[];
    int t = threadIdx.x;
    if (blockIdx.x < BB) {
        float* enc = (float*)smraw;           // [HD]
        float* pq  = enc + HD;                // [4][HD]
        float* pvv = pq + 4 * HD;             // [4][HD]
        float4* zs4 = (float4*)(pvv + 4 * HD);// [64][16] float4
        int b = blockIdx.x;
        if (t < HD) enc[t] = ehs[b * HD + t] + ehs[BB * HD + b * HD + t];
        __syncthreads();
        // qenc/venc with 4-way d-split
        {
            int h = t & 255, p = t >> 8;       // p in 0..3
            float aq = 0.f, av = 0.f;
#pragma unroll 16
            for (int d = p * 64; d < p * 64 + 64; d++) {
                float ev = enc[d];
                aq += ev * wq[d * HD + h];
                av += ev * wv[d * HD + h];
            }
            pq[p * HD + h] = aq;
            pvv[p * HD + h] = av;
        }
        // zsum: 64-way key split, float4 over e
        {
            int e4 = t & 15, p = t >> 4;       // p in 0..63
            const float4* zp4 = (const float4*)(z + (size_t)b * SL * ZD);
            float4 sm = make_float4(0.f, 0.f, 0.f, 0.f);
#pragma unroll 8
            for (int k = p * 32; k < p * 32 + 32; k++) {
                float4 v = zp4[(size_t)k * 16 + e4];
                sm.x += v.x; sm.y += v.y; sm.z += v.z; sm.w += v.w;
            }
            zs4[p * 16 + e4] = sm;
        }
        __syncthreads();
        if (t < HD) {
            g_qenc[b][t] = (pq[0 * HD + t] + pq[1 * HD + t]) +
                           (pq[2 * HD + t] + pq[3 * HD + t]);
            g_venc[b][t] = (pvv[0 * HD + t] + pvv[1 * HD + t]) +
                           (pvv[2 * HD + t] + pvv[3 * HD + t]);
        } else if (t < HD + ZD) {
            int e = t - HD;
            const float* zsf = (const float*)zs4;
            float sm = 0.f;
#pragma unroll
            for (int p = 0; p < 64; p++) sm += zsf[p * ZD + e];
            g_zsum[b][e] = sm;
        }
    } else {
        // M[d][e] = sum_h Wq_z[d,h] * Wk_z[e,h], smem-staged, 1 row/thread
        float (*kz)[KZP] = (float (*)[KZP])smraw;                  // [ZD][KZP]
        float (*qz)[KZP] = (float (*)[KZP])(smraw + ZD * KZP * 4); // [16][KZP]
        int i = blockIdx.x - BB;
#pragma unroll
        for (int r = 0; r < 4; r++) {
            int idx = t + r * 1024;
            int e = idx >> 6, f4 = idx & 63;
            float4 v = *((const float4*)(wk + (size_t)(HD + e) * HD) + f4);
            *((float4*)&kz[e][0] + f4) = v;
        }
        {
            int dl = t >> 6, f4 = t & 63;
            float4 v = *((const float4*)(wq + (size_t)(HD + i * 16 + dl) * HD) + f4);
            *((float4*)&qz[dl][0] + f4) = v;
        }
        __syncthreads();
        int e = t & 63, jg = t >> 6;
        float a0 = 0.f;
#pragma unroll 8
        for (int h4 = 0; h4 < HD / 4; h4++) {
            float4 kv = *((const float4*)&kz[e][0] + h4);
            float4 q0 = *((const float4*)&qz[jg][0] + h4);
            a0 += q0.x * kv.x + q0.y * kv.y + q0.z * kv.z + q0.w * kv.w;
        }
        g_M[i * 16 + jg][e] = a0;
    }
}

// ===== kernel 2: wT[b,d,k] = (M z_k)[d]/16, c[b,k] = (u_b.z_k)/16 ==========
__global__ void k_wc(const float* __restrict__ z,
                     const float* __restrict__ wk) {
    __shared__ float Ms[ZD][ZD];
    __shared__ float qe[HD];
    __shared__ float ps[4][ZD];
    __shared__ float us[ZD];
    int t = threadIdx.x;
    int b = blockIdx.x >> 4;
    int k0 = (blockIdx.x & 15) * 128;
    for (int i = t; i < ZD * ZD / 4; i += 256)
        ((float4*)Ms)[i] = ((const float4*)g_M)[i];
    qe[t] = g_qenc[b][t];
    __syncthreads();
    {
        int e = t & 63, part = t >> 6;
        const float4* wr = (const float4*)(wk + (size_t)(HD + e) * HD) + part * 16;
        const float4* qr = (const float4*)qe + part * 16;
        float pu = 0.f;
#pragma unroll
        for (int i = 0; i < 16; i++) {
            float4 w4 = wr[i], q4 = qr[i];
            pu += q4.x * w4.x + q4.y * w4.y + q4.z * w4.z + q4.w * w4.w;
        }
        ps[part][e] = pu;
    }
    __syncthreads();
    if (t < ZD) us[t] = (ps[0][t] + ps[1][t]) + (ps[2][t] + ps[3][t]);
    __syncthreads();

    int key = k0 + (t & 127);
    int dh = t >> 7;
    const float4* zp4 = (const float4*)(z + ((size_t)b * SL + key) * ZD);
    float zr[ZD];
#pragma unroll
    for (int i = 0; i < ZD / 4; i++) {
        float4 v = zp4[i];
        zr[4 * i + 0] = v.x; zr[4 * i + 1] = v.y;
        zr[4 * i + 2] = v.z; zr[4 * i + 3] = v.w;
    }
    const float inv_t = 0.0625f;
    if (dh == 0) {
        float cacc = 0.f;
#pragma unroll
        for (int e = 0; e < ZD; e++) cacc += zr[e] * us[e];
        g_c[b][key] = cacc * inv_t;
    }
    float* wt = g_wT + (size_t)b * ZD * SL;
#pragma unroll
    for (int d4 = dh * 8; d4 < dh * 8 + 8; d4++) {
        float a0 = 0.f, a1 = 0.f, a2 = 0.f, a3 = 0.f;
#pragma unroll
        for (int e4 = 0; e4 < ZD / 4; e4++) {
            float4 m0 = ((const float4*)&Ms[4 * d4 + 0][0])[e4];
            float4 m1 = ((const float4*)&Ms[4 * d4 + 1][0])[e4];
            float4 m2 = ((const float4*)&Ms[4 * d4 + 2][0])[e4];
            float4 m3 = ((const float4*)&Ms[4 * d4 + 3][0])[e4];
            float z0 = zr[4 * e4 + 0], z1 = zr[4 * e4 + 1];
            float z2 = zr[4 * e4 + 2], z3 = zr[4 * e4 + 3];
            a0 += m0.x * z0 + m0.y * z1 + m0.z * z2 + m0.w * z3;
            a1 += m1.x * z0 + m1.y * z1 + m1.z * z2 + m1.w * z3;
            a2 += m2.x * z0 + m2.y * z1 + m2.z * z2 + m2.w * z3;
            a3 += m3.x * z0 + m3.y * z1 + m3.z * z2 + m3.w * z3;
        }
        wt[(size_t)(4 * d4 + 0) * SL + key] = a0 * inv_t;
        wt[(size_t)(4 * d4 + 1) * SL + key] = a1 * inv_t;
        wt[(size_t)(4 * d4 + 2) * SL + key] = a2 * inv_t;
        wt[(size_t)(4 * d4 + 3) * SL + key] = a3 * inv_t;
    }
}

// =================== kernel 3: scores + softmax + output ===================
// QT=8, 256 threads, 2 CTAs/SM. 8q x 4k micro-tile, KC=512, 32 stages.
struct __align__(16) AttnSmem {
    float  sc[QT][SL];        //  65536 B: scores -> exp values
    float  w[2][ES][KC];      //  32768 B: double-buffered w stages
    float  zq[QT][ZD];        //   2048 B
    float  yT[ZD][QT];        //   2048 B
    float  pv[QT][CAP];       //   4096 B
    int    kv[QT][CAP];       //   4096 B
    int    cnt[QT];
};                             // ~110,640 B -> 2 CTAs/SM

__global__ void __launch_bounds__(256, 2)
k_attn(const float* __restrict__ z, const float* __restrict__ wv,
       const int* __restrict__ mask, float* __restrict__ outp,
       float* __restrict__ attnp) {
    extern __shared__ char smraw[];
    AttnSmem& s = *reinterpret_cast<AttnSmem*>(smraw);
    int t = threadIdx.x;
    int b = blockIdx.x >> 8;           // 256 q-tiles per batch
    int q0 = (blockIdx.x & 255) * QT;

    const float* gwT = g_wT + (size_t)b * ZD * SL;

    // fill zq [QT][ZD] (512 elems over 256 threads)
#pragma unroll
    for (int i = 0; i < 2; i++) {
        int idx = t + i * 256;
        int q = idx >> 6, e = idx & 63;
        s.zq[q][e] = z[((size_t)b * SL + q0 + q) * ZD + e];
    }

    // prefetch stage 0: 8 rows x 512 keys = 1024 float4 over 256 threads
#pragma unroll
    for (int i = 0; i < 4; i++) {
        int idx = t + i * 256;
        int el = idx >> 7, f4 = idx & 127;
        uint32_t sa = (uint32_t)__cvta_generic_to_shared(&s.w[0][el][f4 * 4]);
        cp16(sa, gwT + (size_t)el * SL + f4 * 4);
    }
    cp_commit();

    int kq = t & 127, qg = t >> 7;     // 2 q-groups of 4 rows; 128 k-threads
    int kk = kq * 4;
    ull acc2[4][2];

    // ---- pipelined score GEMM over 32 stages (4 chunks x 8 e-slices) ----
    for (int st = 0; st < NST; st++) {
        cp_wait0();
        __syncthreads();

        int nst = st + 1;
        if (nst < NST) {
            int nch = nst >> 3, nes = nst & 7;
#pragma unroll
            for (int i = 0; i < 4; i++) {
                int idx = t + i * 256;
                int el = idx >> 7, f4 = idx & 127;
                uint32_t sa = (uint32_t)__cvta_generic_to_shared(
                    &s.w[nst & 1][el][f4 * 4]);
                cp16(sa, gwT + (size_t)(nes * ES + el) * SL + nch * KC + f4 * 4);
            }
            cp_commit();
        }

        int ch = st >> 3, es = st & 7, buf = st & 1;
        int k0 = ch * KC;
        if (es == 0) {
            ulonglong2 cv2 = *((const ulonglong2*)&g_c[b][k0 + kk]);
#pragma unroll
            for (int i = 0; i < 4; i++) { acc2[i][0] = cv2.x; acc2[i][1] = cv2.y; }
        }
        int eb = es * ES;
#pragma unroll
        for (int e4 = 0; e4 < 2; e4++) {
            const int el = e4 * 4;
            ulonglong2 b0 = *(const ulonglong2*)&s.w[buf][el + 0][kk];
            ulonglong2 b1 = *(const ulonglong2*)&s.w[buf][el + 1][kk];
            ulonglong2 b2 = *(const ulonglong2*)&s.w[buf][el + 2][kk];
            ulonglong2 b3 = *(const ulonglong2*)&s.w[buf][el + 3][kk];
#pragma unroll
            for (int i = 0; i < 4; i++) {
                float4 a = *(const float4*)&s.zq[4 * qg + i][eb + el];
                ull ax = dup2(a.x), ay = dup2(a.y);
                ull az = dup2(a.z), aw = dup2(a.w);
                fma2(acc2[i][0], ax, b0.x); fma2(acc2[i][1], ax, b0.y);
                fma2(acc2[i][0], ay, b1.x); fma2(acc2[i][1], ay, b1.y);
                fma2(acc2[i][0], az, b2.x); fma2(acc2[i][1], az, b2.y);
                fma2(acc2[i][0], aw, b3.x); fma2(acc2[i][1], aw, b3.y);
            }
        }
        if (es == 7) {
#pragma unroll
            for (int i = 0; i < 4; i++)
                *((ulonglong2*)&s.sc[4 * qg + i][k0 + kk]) =
                    make_ulonglong2(acc2[i][0], acc2[i][1]);
        }
    }
    __syncthreads();

    // ---- per-row softmax: 8 warps, one row each ----
    int w_id = t >> 5, lane = t & 31;
    const float* zb = z + (size_t)b * SL * ZD;
    {
        int r = w_id;
        int msk = mask[b * SL + q0 + r];
        if (lane == 0) s.cnt[r] = 0;
        __syncwarp();

        float4* ap = attnp ? (float4*)(attnp + (size_t)(b * SL + q0 + r) * SL)
                           : (float4*)0;
        float y0 = 0.f, y1 = 0.f;
        if (msk == 0) {
            if (ap) {
                const float u = 1.0f / 2048.0f;
                float4 u4 = make_float4(u, u, u, u);
#pragma unroll
                for (int i = 0; i < 16; i++) __stcs(&ap[i * 32 + lane], u4);
            }
            y0 = g_zsum[b][lane] * (1.0f / 2048.0f);
            y1 = g_zsum[b][lane + 32] * (1.0f / 2048.0f);
        } else {
            const float4* row4 = (const float4*)&s.sc[r][0];
            float4* row4w = (float4*)&s.sc[r][0];
            // sweep 1: row max
            float mx = -3.4e38f;
#pragma unroll
            for (int i = 0; i < 16; i++) {
                float4 v = row4[i * 32 + lane];
                mx = fmaxf(mx, fmaxf(fmaxf(v.x, v.y), fmaxf(v.z, v.w)));
            }
#pragma unroll
            for (int o = 16; o; o >>= 1) mx = fmaxf(mx, __shfl_xor_sync(~0u, mx, o));
            // sweep 2: exp + Z + list; dead windows -> direct zero store
            float Zp = 0.f;
            unsigned live = 0;
            float4 zero4 = make_float4(0.f, 0.f, 0.f, 0.f);
            for (int i = 0; i < 16; i++) {
                int idx = i * 32 + lane;
                float4 v = row4[idx];
                float d0 = v.x - mx, d1 = v.y - mx, d2 = v.z - mx, d3 = v.w - mx;
                float dm = fmaxf(fmaxf(d0, d1), fmaxf(d2, d3));
                unsigned bal = __ballot_sync(~0u, dm >= SKIP_T);
                if (bal == 0) {
                    if (ap) __stcs(&ap[idx], zero4);
                    continue;
                }
                live |= 1u << i;
                float p0 = __expf(d0), p1 = __expf(d1);
                float p2 = __expf(d2), p3 = __expf(d3);
                row4w[idx] = make_float4(p0, p1, p2, p3);
                Zp += (p0 + p1) + (p2 + p3);
                int kb = idx * 4;
                if (p0 > 0.f) { int p = atomicAdd(&s.cnt[r], 1); if (p < CAP) { s.kv[r][p] = kb + 0; s.pv[r][p] = p0; } }
                if (p1 > 0.f) { int p = atomicAdd(&s.cnt[r], 1); if (p < CAP) { s.kv[r][p] = kb + 1; s.pv[r][p] = p1; } }
                if (p2 > 0.f) { int p = atomicAdd(&s.cnt[r], 1); if (p < CAP) { s.kv[r][p] = kb + 2; s.pv[r][p] = p2; } }
                if (p3 > 0.f) { int p = atomicAdd(&s.cnt[r], 1); if (p < CAP) { s.kv[r][p] = kb + 3; s.pv[r][p] = p3; } }
            }
#pragma unroll
            for (int o = 16; o; o >>= 1) Zp += __shfl_xor_sync(~0u, Zp, o);
            float iz = 1.0f / Zp;
            // sweep 3: normalize + store only live windows
            if (ap) {
                unsigned lv = live;
                while (lv) {
                    int i = __ffs(lv) - 1;
                    lv &= lv - 1;
                    int idx = i * 32 + lane;
                    float4 p = row4[idx];
                    __stcs(&ap[idx],
                           make_float4(p.x * iz, p.y * iz, p.z * iz, p.w * iz));
                }
            }
            // y accumulation
            int cnt = s.cnt[r];
            if (cnt <= CAP) {
                for (int i = 0; i < cnt; i++) {
                    float a = s.pv[r][i] * iz;
                    int k = s.kv[r][i];
                    y0 += a * zb[(size_t)k * ZD + lane];
                    y1 += a * zb[(size_t)k * ZD + lane + 32];
                }
            } else {
                unsigned lv = live;
                while (lv) {
                    int i = __ffs(lv) - 1;
                    lv &= lv - 1;
                    for (int k = i * 128; k < i * 128 + 128; k++) {
                        float p = s.sc[r][k];
                        if (p != 0.f) {
                            float a = p * iz;
                            y0 += a * zb[(size_t)k * ZD + lane];
                            y1 += a * zb[(size_t)k * ZD + lane + 32];
                        }
                    }
                }
            }
        }
        s.yT[lane][r] = y0;
        s.yT[lane + 32][r] = y1;
    }
    __syncthreads();

    // ---- output epilogue: packed f32x2, wv from L2 (co-CTA hides latency) --
    if (outp) {
        int h = t;
        float ve = g_venc[b][h];
        ull ved = dup2(ve);
        ull acc[4];
#pragma unroll
        for (int j = 0; j < 4; j++) acc[j] = ved;
#pragma unroll 8
        for (int e = 0; e < ZD; e++) {
            float wvv = __ldg(&wv[(size_t)(HD + e) * HD + h]);
            ull wd = dup2(wvv);
            const ulonglong2* yr = (const ulonglong2*)&s.yT[e][0];
            ulonglong2 ya = yr[0], yb2 = yr[1];
            fma2(acc[0], wd, ya.x);  fma2(acc[1], wd, ya.y);
            fma2(acc[2], wd, yb2.x); fma2(acc[3], wd, yb2.y);
        }
#pragma unroll
        for (int j = 0; j < 4; j++) {
            float lo, hi;
            unpack2(lo, hi, acc[j]);
            outp[((size_t)b * SL + q0 + 2 * j + 0) * HD + h] = lo;
            outp[((size_t)b * SL + q0 + 2 * j + 1) * HD + h] = hi;
        }
    }
}

// ============================== launch =====================================
extern "C" void kernel_launch(void* const* d_in, const int* in_sizes, int n_in,
                              void* d_out, int out_size) {
    const float* ehs  = (const float*)d_in[0];
    // d_in[1] = decoder_hidden_state (unused by reference)
    const float* z    = (const float*)d_in[2];
    const int*   mask = (const int*)d_in[3];
    const float* wq   = (const float*)d_in[4];
    const float* wk   = (const float*)d_in[5];
    const float* wv   = (const float*)d_in[6];

    const long OUT_N = (long)BB * SL * HD;   //  4,194,304
    const long ATT_N = (long)BB * SL * SL;   // 33,554,432
    float* o = (float*)d_out;
    float* outp = nullptr;
    float* attnp = nullptr;
    if ((long)out_size >= OUT_N + ATT_N) { outp = o; attnp = o + OUT_N; }
    else if ((long)out_size == ATT_N)    { attnp = o; }
    else                                 { outp = o; }

    const int PREP_SMEM = (ZD + 16) * KZP * 4;   // 83200 B (M part dominates)

    static int attr_set = 0;
    if (!attr_set) {
        cudaFuncSetAttribute(k_attn, cudaFuncAttributeMaxDynamicSharedMemorySize,
                             (int)sizeof(AttnSmem));
        cudaFuncSetAttribute(k_prep, cudaFuncAttributeMaxDynamicSharedMemorySize,
                             PREP_SMEM);
        attr_set = 1;
    }

    k_prep<<<BB + 4, 1024, PREP_SMEM>>>(ehs, z, wq, wk, wv);
    k_wc<<<128, 256>>>(z, wk);
    k_attn<<<BB * (SL / QT), 256, sizeof(AttnSmem)>>>(z, wv, mask, outp, attnp);
}

// round 14
// speedup vs baseline: 1.1067x; 1.1067x over previous
#include <cuda_runtime.h>
#include <math.h>
#include <stdint.h>
#include <stddef.h>

// ---- problem constants ----
#define HD  256      // HIDDEN_DIM
#define ZD  64       // Z_DIM
#define BB  8        // batch
#define SL  2048     // SRC_LEN
#define QT  16       // queries per tile in k_attn
#define KC  1024     // key chunk in k_attn
#define ES  8        // e-rows per pipeline stage
#define NST 16       // stages = (SL/KC) * (ZD/ES)
#define NTILE (BB * (SL / QT))   // 1024 q-tiles
#define NCTA 148                 // persistent CTAs
#define CAP 128      // per-row nonzero-attn list capacity
#define SKIP_T (-88.0f)
#define KZP 260      // padded smem row (floats) for prep M-part

typedef unsigned long long ull;

// ---- device scratch (no allocation allowed) ----
__device__ float g_venc[BB][HD];
__device__ float g_qenc[BB][HD];
__device__ float g_zsum[BB][ZD];
__device__ float g_M[ZD][ZD];
__device__ float g_wT[BB * ZD * SL]; // [b][d][key], w = (M z_k)/16
__device__ float g_c[BB][SL];        // c_k = (u_b . z_k)/16

// ---- packed fp32x2 helpers ----
__device__ __forceinline__ void fma2(ull& d, ull a, ull b) {
    asm("fma.rn.f32x2 %0, %1, %2, %0;" : "+l"(d) : "l"(a), "l"(b));
}
__device__ __forceinline__ ull dup2(float x) {
    ull r;
    asm("mov.b64 %0, {%1, %1};" : "=l"(r) : "f"(x));
    return r;
}
__device__ __forceinline__ void unpack2(float& lo, float& hi, ull v) {
    asm("mov.b64 {%0, %1}, %2;" : "=f"(lo), "=f"(hi) : "l"(v));
}

// ---- cp.async helpers ----
__device__ __forceinline__ void cp16(uint32_t saddr, const void* gaddr) {
    asm volatile("cp.async.cg.shared.global [%0], [%1], 16;"
                 :: "r"(saddr), "l"(gaddr));
}
__device__ __forceinline__ void cp_commit() {
    asm volatile("cp.async.commit_group;");
}
__device__ __forceinline__ void cp_wait0() {
    asm volatile("cp.async.wait_group 0;");
}

// ====== kernel 1 (fused): blocks 0..7 per-batch consts; 8..11 M tiles ======
__global__ void __launch_bounds__(1024, 1)
k_prep(const float* __restrict__ ehs,
       const float* __restrict__ z,
       const float* __restrict__ wq,
       const float* __restrict__ wk,
       const float* __restrict__ wv) {
    extern __shared__ char smraw[];
    int t = threadIdx.x;
    if (blockIdx.x < BB) {
        float* enc = (float*)smraw;           // [HD]
        float* pq  = enc + HD;                // [4][HD]
        float* pvv = pq + 4 * HD;             // [4][HD]
        float4* zs4 = (float4*)(pvv + 4 * HD);// [64][16] float4
        int b = blockIdx.x;
        if (t < HD) enc[t] = ehs[b * HD + t] + ehs[BB * HD + b * HD + t];
        __syncthreads();
        // qenc/venc with 4-way d-split
        {
            int h = t & 255, p = t >> 8;       // p in 0..3
            float aq = 0.f, av = 0.f;
#pragma unroll 16
            for (int d = p * 64; d < p * 64 + 64; d++) {
                float ev = enc[d];
                aq += ev * wq[d * HD + h];
                av += ev * wv[d * HD + h];
            }
            pq[p * HD + h] = aq;
            pvv[p * HD + h] = av;
        }
        // zsum: 64-way key split, float4 over e
        {
            int e4 = t & 15, p = t >> 4;       // p in 0..63
            const float4* zp4 = (const float4*)(z + (size_t)b * SL * ZD);
            float4 sm = make_float4(0.f, 0.f, 0.f, 0.f);
#pragma unroll 8
            for (int k = p * 32; k < p * 32 + 32; k++) {
                float4 v = zp4[(size_t)k * 16 + e4];
                sm.x += v.x; sm.y += v.y; sm.z += v.z; sm.w += v.w;
            }
            zs4[p * 16 + e4] = sm;
        }
        __syncthreads();
        if (t < HD) {
            g_qenc[b][t] = (pq[0 * HD + t] + pq[1 * HD + t]) +
                           (pq[2 * HD + t] + pq[3 * HD + t]);
            g_venc[b][t] = (pvv[0 * HD + t] + pvv[1 * HD + t]) +
                           (pvv[2 * HD + t] + pvv[3 * HD + t]);
        } else if (t < HD + ZD) {
            int e = t - HD;
            const float* zsf = (const float*)zs4;
            float sm = 0.f;
#pragma unroll
            for (int p = 0; p < 64; p++) sm += zsf[p * ZD + e];
            g_zsum[b][e] = sm;
        }
    } else {
        // M[d][e] = sum_h Wq_z[d,h] * Wk_z[e,h], smem-staged, 1 row/thread
        float (*kz)[KZP] = (float (*)[KZP])smraw;                  // [ZD][KZP]
        float (*qz)[KZP] = (float (*)[KZP])(smraw + ZD * KZP * 4); // [16][KZP]
        int i = blockIdx.x - BB;
#pragma unroll
        for (int r = 0; r < 4; r++) {
            int idx = t + r * 1024;
            int e = idx >> 6, f4 = idx & 63;
            float4 v = *((const float4*)(wk + (size_t)(HD + e) * HD) + f4);
            *((float4*)&kz[e][0] + f4) = v;
        }
        {
            int dl = t >> 6, f4 = t & 63;
            float4 v = *((const float4*)(wq + (size_t)(HD + i * 16 + dl) * HD) + f4);
            *((float4*)&qz[dl][0] + f4) = v;
        }
        __syncthreads();
        int e = t & 63, jg = t >> 6;
        float a0 = 0.f;
#pragma unroll 8
        for (int h4 = 0; h4 < HD / 4; h4++) {
            float4 kv = *((const float4*)&kz[e][0] + h4);
            float4 q0 = *((const float4*)&qz[jg][0] + h4);
            a0 += q0.x * kv.x + q0.y * kv.y + q0.z * kv.z + q0.w * kv.w;
        }
        g_M[i * 16 + jg][e] = a0;
    }
}

// ===== kernel 2: wT[b,d,k] = (M z_k)[d]/16, c[b,k] = (u_b.z_k)/16 ==========
__global__ void k_wc(const float* __restrict__ z,
                     const float* __restrict__ wk) {
    __shared__ float Ms[ZD][ZD];
    __shared__ float qe[HD];
    __shared__ float ps[4][ZD];
    __shared__ float us[ZD];
    int t = threadIdx.x;
    int b = blockIdx.x >> 4;
    int k0 = (blockIdx.x & 15) * 128;
    for (int i = t; i < ZD * ZD / 4; i += 256)
        ((float4*)Ms)[i] = ((const float4*)g_M)[i];
    qe[t] = g_qenc[b][t];
    __syncthreads();
    {
        int e = t & 63, part = t >> 6;
        const float4* wr = (const float4*)(wk + (size_t)(HD + e) * HD) + part * 16;
        const float4* qr = (const float4*)qe + part * 16;
        float pu = 0.f;
#pragma unroll
        for (int i = 0; i < 16; i++) {
            float4 w4 = wr[i], q4 = qr[i];
            pu += q4.x * w4.x + q4.y * w4.y + q4.z * w4.z + q4.w * w4.w;
        }
        ps[part][e] = pu;
    }
    __syncthreads();
    if (t < ZD) us[t] = (ps[0][t] + ps[1][t]) + (ps[2][t] + ps[3][t]);
    __syncthreads();

    int key = k0 + (t & 127);
    int dh = t >> 7;
    const float4* zp4 = (const float4*)(z + ((size_t)b * SL + key) * ZD);
    float zr[ZD];
#pragma unroll
    for (int i = 0; i < ZD / 4; i++) {
        float4 v = zp4[i];
        zr[4 * i + 0] = v.x; zr[4 * i + 1] = v.y;
        zr[4 * i + 2] = v.z; zr[4 * i + 3] = v.w;
    }
    const float inv_t = 0.0625f;
    if (dh == 0) {
        float cacc = 0.f;
#pragma unroll
        for (int e = 0; e < ZD; e++) cacc += zr[e] * us[e];
        g_c[b][key] = cacc * inv_t;
    }
    float* wt = g_wT + (size_t)b * ZD * SL;
#pragma unroll
    for (int d4 = dh * 8; d4 < dh * 8 + 8; d4++) {
        float a0 = 0.f, a1 = 0.f, a2 = 0.f, a3 = 0.f;
#pragma unroll
        for (int e4 = 0; e4 < ZD / 4; e4++) {
            float4 m0 = ((const float4*)&Ms[4 * d4 + 0][0])[e4];
            float4 m1 = ((const float4*)&Ms[4 * d4 + 1][0])[e4];
            float4 m2 = ((const float4*)&Ms[4 * d4 + 2][0])[e4];
            float4 m3 = ((const float4*)&Ms[4 * d4 + 3][0])[e4];
            float z0 = zr[4 * e4 + 0], z1 = zr[4 * e4 + 1];
            float z2 = zr[4 * e4 + 2], z3 = zr[4 * e4 + 3];
            a0 += m0.x * z0 + m0.y * z1 + m0.z * z2 + m0.w * z3;
            a1 += m1.x * z0 + m1.y * z1 + m1.z * z2 + m1.w * z3;
            a2 += m2.x * z0 + m2.y * z1 + m2.z * z2 + m2.w * z3;
            a3 += m3.x * z0 + m3.y * z1 + m3.z * z2 + m3.w * z3;
        }
        wt[(size_t)(4 * d4 + 0) * SL + key] = a0 * inv_t;
        wt[(size_t)(4 * d4 + 1) * SL + key] = a1 * inv_t;
        wt[(size_t)(4 * d4 + 2) * SL + key] = a2 * inv_t;
        wt[(size_t)(4 * d4 + 3) * SL + key] = a3 * inv_t;
    }
}

// =================== kernel 3: persistent scores + softmax + output ========
struct __align__(16) AttnSmem {
    float  sc[QT][SL];        // 131072 B: scores -> exp values
    float  w[2][ES][KC];      //  65536 B: w stages; later wv slice [64][256]
    float  zq[QT][ZD];        //   4096 B
    float  yT[ZD][QT];        //   4096 B
    float  pv[QT][CAP];       //   8192 B
    int    kv[QT][CAP];       //   8192 B
    int    cnt[QT];
};

__global__ void __launch_bounds__(512, 1)
k_attn(const float* __restrict__ z, const float* __restrict__ wv,
       const int* __restrict__ mask, float* __restrict__ outp,
       float* __restrict__ attnp) {
    extern __shared__ char smraw[];
    AttnSmem& s = *reinterpret_cast<AttnSmem*>(smraw);
    int t = threadIdx.x;

    for (int tile = blockIdx.x; tile < NTILE; tile += NCTA) {
        int b = tile >> 7;
        int q0 = (tile & 127) * QT;
        const float* gwT = g_wT + (size_t)b * ZD * SL;

        // guard: all warps done with previous tile's smem (wvs/yT) before
        // overwriting zq / issuing new w prefetch into the shared buffers
        __syncthreads();

        // fill zq [QT][ZD]
#pragma unroll
        for (int i = 0; i < 2; i++) {
            int idx = t + i * 512;
            int q = idx >> 6, e = idx & 63;
            s.zq[q][e] = z[((size_t)b * SL + q0 + q) * ZD + e];
        }

        // prefetch stage 0
#pragma unroll
        for (int i = 0; i < 4; i++) {
            int idx = t + i * 512;
            int el = idx >> 8, f4 = idx & 255;
            uint32_t sa = (uint32_t)__cvta_generic_to_shared(&s.w[0][el][f4 * 4]);
            cp16(sa, gwT + (size_t)el * SL + f4 * 4);
        }
        cp_commit();

        int kq = t & 255, qg = t >> 8;
        int kk = kq * 4;
        ull acc2[8][2];

        // ---- pipelined score GEMM over 16 stages (2 chunks x 8 e-slices) --
        for (int st = 0; st < NST; st++) {
            cp_wait0();
            __syncthreads();

            int nst = st + 1;
            if (nst < NST) {
                int nch = nst >> 3, nes = nst & 7;
#pragma unroll
                for (int i = 0; i < 4; i++) {
                    int idx = t + i * 512;
                    int el = idx >> 8, f4 = idx & 255;
                    uint32_t sa = (uint32_t)__cvta_generic_to_shared(
                        &s.w[nst & 1][el][f4 * 4]);
                    cp16(sa, gwT + (size_t)(nes * ES + el) * SL + nch * KC + f4 * 4);
                }
                cp_commit();
            }

            int ch = st >> 3, es = st & 7, buf = st & 1;
            int k0 = ch * KC;
            if (es == 0) {
                ulonglong2 cv2 = *((const ulonglong2*)&g_c[b][k0 + kk]);
#pragma unroll
                for (int i = 0; i < 8; i++) { acc2[i][0] = cv2.x; acc2[i][1] = cv2.y; }
            }
            int eb = es * ES;
#pragma unroll
            for (int e4 = 0; e4 < 2; e4++) {
                const int el = e4 * 4;
                ulonglong2 b0 = *(const ulonglong2*)&s.w[buf][el + 0][kk];
                ulonglong2 b1 = *(const ulonglong2*)&s.w[buf][el + 1][kk];
                ulonglong2 b2 = *(const ulonglong2*)&s.w[buf][el + 2][kk];
                ulonglong2 b3 = *(const ulonglong2*)&s.w[buf][el + 3][kk];
#pragma unroll
                for (int i = 0; i < 8; i++) {
                    float4 a = *(const float4*)&s.zq[8 * qg + i][eb + el];
                    ull ax = dup2(a.x), ay = dup2(a.y);
                    ull az = dup2(a.z), aw = dup2(a.w);
                    fma2(acc2[i][0], ax, b0.x); fma2(acc2[i][1], ax, b0.y);
                    fma2(acc2[i][0], ay, b1.x); fma2(acc2[i][1], ay, b1.y);
                    fma2(acc2[i][0], az, b2.x); fma2(acc2[i][1], az, b2.y);
                    fma2(acc2[i][0], aw, b3.x); fma2(acc2[i][1], aw, b3.y);
                }
            }
            if (es == 7) {
#pragma unroll
                for (int i = 0; i < 8; i++)
                    *((ulonglong2*)&s.sc[8 * qg + i][k0 + kk]) =
                        make_ulonglong2(acc2[i][0], acc2[i][1]);
            }
        }
        __syncthreads();

        // ---- stage wv slice [64][256] into freed w buffer ----
        float* wvs = &s.w[0][0][0];
#pragma unroll
        for (int i = 0; i < 8; i++) {
            int idx = t + i * 512;              // 0..4095 float4s
            int el = idx >> 6, f4 = idx & 63;
            uint32_t sa = (uint32_t)__cvta_generic_to_shared(wvs + (size_t)idx * 4);
            cp16(sa, wv + (size_t)(HD + el) * HD + f4 * 4);
        }
        cp_commit();

        // ---- per-row softmax: 16 warps, one row each ----
        int w_id = t >> 5, lane = t & 31;
        const float* zb = z + (size_t)b * SL * ZD;
        {
            int r = w_id;
            int msk = mask[b * SL + q0 + r];
            if (lane == 0) s.cnt[r] = 0;
            __syncwarp();

            float4* ap = attnp ? (float4*)(attnp + (size_t)(b * SL + q0 + r) * SL)
                               : (float4*)0;
            float y0 = 0.f, y1 = 0.f;
            if (msk == 0) {
                if (ap) {
                    const float u = 1.0f / 2048.0f;
                    float4 u4 = make_float4(u, u, u, u);
#pragma unroll
                    for (int i = 0; i < 16; i++) __stcs(&ap[i * 32 + lane], u4);
                }
                y0 = g_zsum[b][lane] * (1.0f / 2048.0f);
                y1 = g_zsum[b][lane + 32] * (1.0f / 2048.0f);
            } else {
                const float4* row4 = (const float4*)&s.sc[r][0];
                float4* row4w = (float4*)&s.sc[r][0];
                // sweep 1: row max
                float mx = -3.4e38f;
#pragma unroll
                for (int i = 0; i < 16; i++) {
                    float4 v = row4[i * 32 + lane];
                    mx = fmaxf(mx, fmaxf(fmaxf(v.x, v.y), fmaxf(v.z, v.w)));
                }
#pragma unroll
                for (int o = 16; o; o >>= 1) mx = fmaxf(mx, __shfl_xor_sync(~0u, mx, o));
                // sweep 2: exp + Z + list; dead windows -> direct zero store
                float Zp = 0.f;
                unsigned live = 0;
                float4 zero4 = make_float4(0.f, 0.f, 0.f, 0.f);
                for (int i = 0; i < 16; i++) {
                    int idx = i * 32 + lane;
                    float4 v = row4[idx];
                    float d0 = v.x - mx, d1 = v.y - mx, d2 = v.z - mx, d3 = v.w - mx;
                    float dm = fmaxf(fmaxf(d0, d1), fmaxf(d2, d3));
                    unsigned bal = __ballot_sync(~0u, dm >= SKIP_T);
                    if (bal == 0) {
                        if (ap) __stcs(&ap[idx], zero4);
                        continue;
                    }
                    live |= 1u << i;
                    float p0 = __expf(d0), p1 = __expf(d1);
                    float p2 = __expf(d2), p3 = __expf(d3);
                    row4w[idx] = make_float4(p0, p1, p2, p3);
                    Zp += (p0 + p1) + (p2 + p3);
                    int kb = idx * 4;
                    if (p0 > 0.f) { int p = atomicAdd(&s.cnt[r], 1); if (p < CAP) { s.kv[r][p] = kb + 0; s.pv[r][p] = p0; } }
                    if (p1 > 0.f) { int p = atomicAdd(&s.cnt[r], 1); if (p < CAP) { s.kv[r][p] = kb + 1; s.pv[r][p] = p1; } }
                    if (p2 > 0.f) { int p = atomicAdd(&s.cnt[r], 1); if (p < CAP) { s.kv[r][p] = kb + 2; s.pv[r][p] = p2; } }
                    if (p3 > 0.f) { int p = atomicAdd(&s.cnt[r], 1); if (p < CAP) { s.kv[r][p] = kb + 3; s.pv[r][p] = p3; } }
                }
#pragma unroll
                for (int o = 16; o; o >>= 1) Zp += __shfl_xor_sync(~0u, Zp, o);
                float iz = 1.0f / Zp;
                // sweep 3: normalize + store only live windows
                if (ap) {
                    unsigned lv = live;
                    while (lv) {
                        int i = __ffs(lv) - 1;
                        lv &= lv - 1;
                        int idx = i * 32 + lane;
                        float4 p = row4[idx];
                        __stcs(&ap[idx],
                               make_float4(p.x * iz, p.y * iz, p.z * iz, p.w * iz));
                    }
                }
                // y accumulation
                int cnt = s.cnt[r];
                if (cnt <= CAP) {
                    for (int i = 0; i < cnt; i++) {
                        float a = s.pv[r][i] * iz;
                        int k = s.kv[r][i];
                        y0 += a * zb[(size_t)k * ZD + lane];
                        y1 += a * zb[(size_t)k * ZD + lane + 32];
                    }
                } else {
                    unsigned lv = live;
                    while (lv) {
                        int i = __ffs(lv) - 1;
                        lv &= lv - 1;
                        for (int k = i * 128; k < i * 128 + 128; k++) {
                            float p = s.sc[r][k];
                            if (p != 0.f) {
                                float a = p * iz;
                                y0 += a * zb[(size_t)k * ZD + lane];
                                y1 += a * zb[(size_t)k * ZD + lane + 32];
                            }
                        }
                    }
                }
            }
            s.yT[lane][r] = y0;
            s.yT[lane + 32][r] = y1;
        }
        cp_wait0();
        __syncthreads();

        // ---- output epilogue: packed f32x2, wv from smem ----
        if (outp) {
            int h = t & 255, qh = t >> 8;
            float ve = g_venc[b][h];
            ull ved = dup2(ve);
            ull acc[4];
#pragma unroll
            for (int j = 0; j < 4; j++) acc[j] = ved;
#pragma unroll 8
            for (int e = 0; e < ZD; e++) {
                float wvv = wvs[e * HD + h];
                ull wd = dup2(wvv);
                const ulonglong2* yr = ((const ulonglong2*)&s.yT[e][0]) + qh * 2;
                ulonglong2 ya = yr[0], yb2 = yr[1];
                fma2(acc[0], wd, ya.x);  fma2(acc[1], wd, ya.y);
                fma2(acc[2], wd, yb2.x); fma2(acc[3], wd, yb2.y);
            }
#pragma unroll
            for (int j = 0; j < 4; j++) {
                float lo, hi;
                unpack2(lo, hi, acc[j]);
                outp[((size_t)b * SL + q0 + qh * 8 + 2 * j + 0) * HD + h] = lo;
                outp[((size_t)b * SL + q0 + qh * 8 + 2 * j + 1) * HD + h] = hi;
            }
        }
    }
}

// ============================== launch =====================================
extern "C" void kernel_launch(void* const* d_in, const int* in_sizes, int n_in,
                              void* d_out, int out_size) {
    const float* ehs  = (const float*)d_in[0];
    // d_in[1] = decoder_hidden_state (unused by reference)
    const float* z    = (const float*)d_in[2];
    const int*   mask = (const int*)d_in[3];
    const float* wq   = (const float*)d_in[4];
    const float* wk   = (const float*)d_in[5];
    const float* wv   = (const float*)d_in[6];

    const long OUT_N = (long)BB * SL * HD;   //  4,194,304
    const long ATT_N = (long)BB * SL * SL;   // 33,554,432
    float* o = (float*)d_out;
    float* outp = nullptr;
    float* attnp = nullptr;
    if ((long)out_size >= OUT_N + ATT_N) { outp = o; attnp = o + OUT_N; }
    else if ((long)out_size == ATT_N)    { attnp = o; }
    else                                 { outp = o; }

    const int PREP_SMEM = (ZD + 16) * KZP * 4;   // 83200 B (M part dominates)

    static int attr_set = 0;
    if (!attr_set) {
        cudaFuncSetAttribute(k_attn, cudaFuncAttributeMaxDynamicSharedMemorySize,
                             (int)sizeof(AttnSmem));
        cudaFuncSetAttribute(k_prep, cudaFuncAttributeMaxDynamicSharedMemorySize,
                             PREP_SMEM);
        attr_set = 1;
    }

    k_prep<<<BB + 4, 1024, PREP_SMEM>>>(ehs, z, wq, wk, wv);
    k_wc<<<128, 256>>>(z, wk);
    k_attn<<<NCTA, 512, sizeof(AttnSmem)>>>(z, wv, mask, outp, attnp);
}

// round 15
// speedup vs baseline: 1.1666x; 1.0542x over previous
#include <cuda_runtime.h>
#include <math.h>
#include <stdint.h>
#include <stddef.h>

// ---- problem constants ----
#define HD  256      // HIDDEN_DIM
#define ZD  64       // Z_DIM
#define BB  8        // batch
#define SL  2048     // SRC_LEN
#define QT  16       // queries per block in k_attn
#define KC  1024     // key chunk in k_attn
#define ES  8        // e-rows per pipeline stage
#define NST 16       // stages = (SL/KC) * (ZD/ES)
#define CAP 128      // per-row nonzero-attn list capacity
#define SKIP_T (-88.0f)
#define KZP 260      // padded smem row (floats) for prep M-part

typedef unsigned long long ull;

// ---- device scratch (no allocation allowed) ----
__device__ float g_venc[BB][HD];
__device__ float g_qenc[BB][HD];
__device__ float g_zsum[BB][ZD];
__device__ float g_M[ZD][ZD];
__device__ float g_wT[BB * ZD * SL]; // [b][d][key], w = (M z_k)/16
__device__ float g_c[BB][SL];        // c_k = (u_b . z_k)/16

// ---- packed fp32x2 helpers ----
__device__ __forceinline__ void fma2(ull& d, ull a, ull b) {
    asm("fma.rn.f32x2 %0, %1, %2, %0;" : "+l"(d) : "l"(a), "l"(b));
}
__device__ __forceinline__ ull dup2(float x) {
    ull r;
    asm("mov.b64 %0, {%1, %1};" : "=l"(r) : "f"(x));
    return r;
}
__device__ __forceinline__ void unpack2(float& lo, float& hi, ull v) {
    asm("mov.b64 {%0, %1}, %2;" : "=f"(lo), "=f"(hi) : "l"(v));
}

// ---- cp.async helpers ----
__device__ __forceinline__ void cp16(uint32_t saddr, const void* gaddr) {
    asm volatile("cp.async.cg.shared.global [%0], [%1], 16;"
                 :: "r"(saddr), "l"(gaddr));
}
__device__ __forceinline__ void cp_commit() {
    asm volatile("cp.async.commit_group;");
}
__device__ __forceinline__ void cp_wait0() {
    asm volatile("cp.async.wait_group 0;");
}
__device__ __forceinline__ void bar_pair(int id) {
    asm volatile("bar.sync %0, 64;" :: "r"(id) : "memory");
}

// ====== kernel 1 (fused): blocks 0..7 per-batch consts; 8..11 M tiles ======
__global__ void __launch_bounds__(1024, 1)
k_prep(const float* __restrict__ ehs,
       const float* __restrict__ z,
       const float* __restrict__ wq,
       const float* __restrict__ wk,
       const float* __restrict__ wv) {
    extern __shared__ char smraw[];
    int t = threadIdx.x;
    if (blockIdx.x < BB) {
        float* enc = (float*)smraw;           // [HD]
        float* pq  = enc + HD;                // [4][HD]
        float* pvv = pq + 4 * HD;             // [4][HD]
        float4* zs4 = (float4*)(pvv + 4 * HD);// [64][16] float4
        int b = blockIdx.x;
        if (t < HD) enc[t] = ehs[b * HD + t] + ehs[BB * HD + b * HD + t];
        __syncthreads();
        // qenc/venc with 4-way d-split
        {
            int h = t & 255, p = t >> 8;       // p in 0..3
            float aq = 0.f, av = 0.f;
#pragma unroll 16
            for (int d = p * 64; d < p * 64 + 64; d++) {
                float ev = enc[d];
                aq += ev * wq[d * HD + h];
                av += ev * wv[d * HD + h];
            }
            pq[p * HD + h] = aq;
            pvv[p * HD + h] = av;
        }
        // zsum: 64-way key split, float4 over e
        {
            int e4 = t & 15, p = t >> 4;       // p in 0..63
            const float4* zp4 = (const float4*)(z + (size_t)b * SL * ZD);
            float4 sm = make_float4(0.f, 0.f, 0.f, 0.f);
#pragma unroll 8
            for (int k = p * 32; k < p * 32 + 32; k++) {
                float4 v = zp4[(size_t)k * 16 + e4];
                sm.x += v.x; sm.y += v.y; sm.z += v.z; sm.w += v.w;
            }
            zs4[p * 16 + e4] = sm;
        }
        __syncthreads();
        if (t < HD) {
            g_qenc[b][t] = (pq[0 * HD + t] + pq[1 * HD + t]) +
                           (pq[2 * HD + t] + pq[3 * HD + t]);
            g_venc[b][t] = (pvv[0 * HD + t] + pvv[1 * HD + t]) +
                           (pvv[2 * HD + t] + pvv[3 * HD + t]);
        } else if (t < HD + ZD) {
            int e = t - HD;
            const float* zsf = (const float*)zs4;
            float sm = 0.f;
#pragma unroll
            for (int p = 0; p < 64; p++) sm += zsf[p * ZD + e];
            g_zsum[b][e] = sm;
        }
    } else {
        // M[d][e] = sum_h Wq_z[d,h] * Wk_z[e,h], smem-staged, 1 row/thread
        float (*kz)[KZP] = (float (*)[KZP])smraw;                  // [ZD][KZP]
        float (*qz)[KZP] = (float (*)[KZP])(smraw + ZD * KZP * 4); // [16][KZP]
        int i = blockIdx.x - BB;
#pragma unroll
        for (int r = 0; r < 4; r++) {
            int idx = t + r * 1024;
            int e = idx >> 6, f4 = idx & 63;
            float4 v = *((const float4*)(wk + (size_t)(HD + e) * HD) + f4);
            *((float4*)&kz[e][0] + f4) = v;
        }
        {
            int dl = t >> 6, f4 = t & 63;
            float4 v = *((const float4*)(wq + (size_t)(HD + i * 16 + dl) * HD) + f4);
            *((float4*)&qz[dl][0] + f4) = v;
        }
        __syncthreads();
        int e = t & 63, jg = t >> 6;
        float a0 = 0.f;
#pragma unroll 8
        for (int h4 = 0; h4 < HD / 4; h4++) {
            float4 kv = *((const float4*)&kz[e][0] + h4);
            float4 q0 = *((const float4*)&qz[jg][0] + h4);
            a0 += q0.x * kv.x + q0.y * kv.y + q0.z * kv.z + q0.w * kv.w;
        }
        g_M[i * 16 + jg][e] = a0;
    }
}

// ===== kernel 2: wT[b,d,k] = (M z_k)[d]/16, c[b,k] = (u_b.z_k)/16 ==========
__global__ void k_wc(const float* __restrict__ z,
                     const float* __restrict__ wk) {
    __shared__ float Ms[ZD][ZD];
    __shared__ float qe[HD];
    __shared__ float ps[4][ZD];
    __shared__ float us[ZD];
    int t = threadIdx.x;
    int b = blockIdx.x >> 4;
    int k0 = (blockIdx.x & 15) * 128;
    for (int i = t; i < ZD * ZD / 4; i += 256)
        ((float4*)Ms)[i] = ((const float4*)g_M)[i];
    qe[t] = g_qenc[b][t];
    __syncthreads();
    {
        int e = t & 63, part = t >> 6;
        const float4* wr = (const float4*)(wk + (size_t)(HD + e) * HD) + part * 16;
        const float4* qr = (const float4*)qe + part * 16;
        float pu = 0.f;
#pragma unroll
        for (int i = 0; i < 16; i++) {
            float4 w4 = wr[i], q4 = qr[i];
            pu += q4.x * w4.x + q4.y * w4.y + q4.z * w4.z + q4.w * w4.w;
        }
        ps[part][e] = pu;
    }
    __syncthreads();
    if (t < ZD) us[t] = (ps[0][t] + ps[1][t]) + (ps[2][t] + ps[3][t]);
    __syncthreads();

    int key = k0 + (t & 127);
    int dh = t >> 7;
    const float4* zp4 = (const float4*)(z + ((size_t)b * SL + key) * ZD);
    float zr[ZD];
#pragma unroll
    for (int i = 0; i < ZD / 4; i++) {
        float4 v = zp4[i];
        zr[4 * i + 0] = v.x; zr[4 * i + 1] = v.y;
        zr[4 * i + 2] = v.z; zr[4 * i + 3] = v.w;
    }
    const float inv_t = 0.0625f;
    if (dh == 0) {
        float cacc = 0.f;
#pragma unroll
        for (int e = 0; e < ZD; e++) cacc += zr[e] * us[e];
        g_c[b][key] = cacc * inv_t;
    }
    float* wt = g_wT + (size_t)b * ZD * SL;
#pragma unroll
    for (int d4 = dh * 8; d4 < dh * 8 + 8; d4++) {
        float a0 = 0.f, a1 = 0.f, a2 = 0.f, a3 = 0.f;
#pragma unroll
        for (int e4 = 0; e4 < ZD / 4; e4++) {
            float4 m0 = ((const float4*)&Ms[4 * d4 + 0][0])[e4];
            float4 m1 = ((const float4*)&Ms[4 * d4 + 1][0])[e4];
            float4 m2 = ((const float4*)&Ms[4 * d4 + 2][0])[e4];
            float4 m3 = ((const float4*)&Ms[4 * d4 + 3][0])[e4];
            float z0 = zr[4 * e4 + 0], z1 = zr[4 * e4 + 1];
            float z2 = zr[4 * e4 + 2], z3 = zr[4 * e4 + 3];
            a0 += m0.x * z0 + m0.y * z1 + m0.z * z2 + m0.w * z3;
            a1 += m1.x * z0 + m1.y * z1 + m1.z * z2 + m1.w * z3;
            a2 += m2.x * z0 + m2.y * z1 + m2.z * z2 + m2.w * z3;
            a3 += m3.x * z0 + m3.y * z1 + m3.z * z2 + m3.w * z3;
        }
        wt[(size_t)(4 * d4 + 0) * SL + key] = a0 * inv_t;
        wt[(size_t)(4 * d4 + 1) * SL + key] = a1 * inv_t;
        wt[(size_t)(4 * d4 + 2) * SL + key] = a2 * inv_t;
        wt[(size_t)(4 * d4 + 3) * SL + key] = a3 * inv_t;
    }
}

// =================== kernel 3: scores + softmax + output ===================
// Per-pair stage buffers: pair p (warps p, p+8) owns keys [p*128, p*128+128)
// of every chunk; loads its own span; syncs with 2-warp named barrier.
struct __align__(16) AttnSmem {
    float  sc[QT][SL];          // 131072 B: scores -> exp values
    float  wp[8][2][ES][128];   //  65536 B: per-pair double-buffered stages
    float  zq[QT][ZD];          //   4096 B
    float  yT[ZD][QT];          //   4096 B
    float  pv[QT][CAP];         //   8192 B
    int    kv[QT][CAP];         //   8192 B
    int    cnt[QT];
};

__global__ void __launch_bounds__(512, 1)
k_attn(const float* __restrict__ z, const float* __restrict__ wv,
       const int* __restrict__ mask, float* __restrict__ outp,
       float* __restrict__ attnp) {
    extern __shared__ char smraw[];
    AttnSmem& s = *reinterpret_cast<AttnSmem*>(smraw);
    int t = threadIdx.x;
    int b = blockIdx.x >> 7;
    int q0 = (blockIdx.x & 127) * QT;

    const float* gwT = g_wT + (size_t)b * ZD * SL;

    int w_id = t >> 5, lane = t & 31;
    int pair = w_id & 7;            // key-span owner
    int half = w_id >> 3;           // 0: q rows 0-7 & e-rows 0-3; 1: rows 8-15 & 4-7
    int qg = half;
    int kq = pair * 32 + lane;      // 0..255 (matches old t&255 mapping)
    int kk = kq * 4;
    // per-warp load slice: rows half*4+j of the pair's 128-key span
    const float* gsp = gwT + (size_t)pair * 128 + (size_t)lane * 4;

    // fill zq [QT][ZD]
#pragma unroll
    for (int i = 0; i < 2; i++) {
        int idx = t + i * 512;
        int q = idx >> 6, e = idx & 63;
        s.zq[q][e] = z[((size_t)b * SL + q0 + q) * ZD + e];
    }
    __syncthreads();   // zq visible to all warps before GEMM

    // prefetch stage 0 (own span only)
#pragma unroll
    for (int j = 0; j < 4; j++) {
        int el = half * 4 + j;
        uint32_t sa = (uint32_t)__cvta_generic_to_shared(
            &s.wp[pair][0][el][lane * 4]);
        cp16(sa, gsp + (size_t)el * SL);
    }
    cp_commit();

    ull acc2[8][2];

    // ---- pipelined score GEMM over 16 stages (2 chunks x 8 e-slices) ----
    for (int st = 0; st < NST; st++) {
        cp_wait0();
        bar_pair(pair + 1);         // partner's half landed; buffer reusable

        int nst = st + 1;
        if (nst < NST) {
            int nch = nst >> 3, nes = nst & 7;
#pragma unroll
            for (int j = 0; j < 4; j++) {
                int el = half * 4 + j;
                uint32_t sa = (uint32_t)__cvta_generic_to_shared(
                    &s.wp[pair][nst & 1][el][lane * 4]);
                cp16(sa, gsp + (size_t)(nes * ES + el) * SL + nch * KC);
            }
            cp_commit();
        }

        int ch = st >> 3, es = st & 7, buf = st & 1;
        int k0 = ch * KC;
        if (es == 0) {
            ulonglong2 cv2 = *((const ulonglong2*)&g_c[b][k0 + kk]);
#pragma unroll
            for (int i = 0; i < 8; i++) { acc2[i][0] = cv2.x; acc2[i][1] = cv2.y; }
        }
        int eb = es * ES;
#pragma unroll
        for (int e4 = 0; e4 < 2; e4++) {
            const int el = e4 * 4;
            ulonglong2 b0 = *(const ulonglong2*)&s.wp[pair][buf][el + 0][lane * 4];
            ulonglong2 b1 = *(const ulonglong2*)&s.wp[pair][buf][el + 1][lane * 4];
            ulonglong2 b2 = *(const ulonglong2*)&s.wp[pair][buf][el + 2][lane * 4];
            ulonglong2 b3 = *(const ulonglong2*)&s.wp[pair][buf][el + 3][lane * 4];
#pragma unroll
            for (int i = 0; i < 8; i++) {
                float4 a = *(const float4*)&s.zq[8 * qg + i][eb + el];
                ull ax = dup2(a.x), ay = dup2(a.y);
                ull az = dup2(a.z), aw = dup2(a.w);
                fma2(acc2[i][0], ax, b0.x); fma2(acc2[i][1], ax, b0.y);
                fma2(acc2[i][0], ay, b1.x); fma2(acc2[i][1], ay, b1.y);
                fma2(acc2[i][0], az, b2.x); fma2(acc2[i][1], az, b2.y);
                fma2(acc2[i][0], aw, b3.x); fma2(acc2[i][1], aw, b3.y);
            }
        }
        if (es == 7) {
#pragma unroll
            for (int i = 0; i < 8; i++)
                *((ulonglong2*)&s.sc[8 * qg + i][k0 + kk]) =
                    make_ulonglong2(acc2[i][0], acc2[i][1]);
        }
    }
    __syncthreads();    // sc complete across all warps

    // ---- stage wv slice [64][256] into freed wp buffer; overlaps softmax ---
    float* wvs = &s.wp[0][0][0][0];
#pragma unroll
    for (int i = 0; i < 8; i++) {
        int idx = t + i * 512;              // 0..4095 float4s
        int el = idx >> 6, f4 = idx & 63;
        uint32_t sa = (uint32_t)__cvta_generic_to_shared(wvs + (size_t)idx * 4);
        cp16(sa, wv + (size_t)(HD + el) * HD + f4 * 4);
    }
    cp_commit();

    // ---- per-row softmax: 16 warps, one row each ----
    const float* zb = z + (size_t)b * SL * ZD;
    {
        int r = w_id;
        int msk = mask[b * SL + q0 + r];
        if (lane == 0) s.cnt[r] = 0;
        __syncwarp();

        float4* ap = attnp ? (float4*)(attnp + (size_t)(b * SL + q0 + r) * SL)
                           : (float4*)0;
        float y0 = 0.f, y1 = 0.f;
        if (msk == 0) {
            if (ap) {
                const float u = 1.0f / 2048.0f;
                float4 u4 = make_float4(u, u, u, u);
#pragma unroll
                for (int i = 0; i < 16; i++) __stcs(&ap[i * 32 + lane], u4);
            }
            y0 = g_zsum[b][lane] * (1.0f / 2048.0f);
            y1 = g_zsum[b][lane + 32] * (1.0f / 2048.0f);
        } else {
            const float4* row4 = (const float4*)&s.sc[r][0];
            float4* row4w = (float4*)&s.sc[r][0];
            // sweep 1: row max
            float mx = -3.4e38f;
#pragma unroll
            for (int i = 0; i < 16; i++) {
                float4 v = row4[i * 32 + lane];
                mx = fmaxf(mx, fmaxf(fmaxf(v.x, v.y), fmaxf(v.z, v.w)));
            }
#pragma unroll
            for (int o = 16; o; o >>= 1) mx = fmaxf(mx, __shfl_xor_sync(~0u, mx, o));
            // sweep 2: exp + Z + list; dead windows -> direct zero store
            float Zp = 0.f;
            unsigned live = 0;
            float4 zero4 = make_float4(0.f, 0.f, 0.f, 0.f);
            for (int i = 0; i < 16; i++) {
                int idx = i * 32 + lane;
                float4 v = row4[idx];
                float d0 = v.x - mx, d1 = v.y - mx, d2 = v.z - mx, d3 = v.w - mx;
                float dm = fmaxf(fmaxf(d0, d1), fmaxf(d2, d3));
                unsigned bal = __ballot_sync(~0u, dm >= SKIP_T);
                if (bal == 0) {
                    if (ap) __stcs(&ap[idx], zero4);
                    continue;
                }
                live |= 1u << i;
                float p0 = __expf(d0), p1 = __expf(d1);
                float p2 = __expf(d2), p3 = __expf(d3);
                row4w[idx] = make_float4(p0, p1, p2, p3);
                Zp += (p0 + p1) + (p2 + p3);
                int kb = idx * 4;
                if (p0 > 0.f) { int p = atomicAdd(&s.cnt[r], 1); if (p < CAP) { s.kv[r][p] = kb + 0; s.pv[r][p] = p0; } }
                if (p1 > 0.f) { int p = atomicAdd(&s.cnt[r], 1); if (p < CAP) { s.kv[r][p] = kb + 1; s.pv[r][p] = p1; } }
                if (p2 > 0.f) { int p = atomicAdd(&s.cnt[r], 1); if (p < CAP) { s.kv[r][p] = kb + 2; s.pv[r][p] = p2; } }
                if (p3 > 0.f) { int p = atomicAdd(&s.cnt[r], 1); if (p < CAP) { s.kv[r][p] = kb + 3; s.pv[r][p] = p3; } }
            }
#pragma unroll
            for (int o = 16; o; o >>= 1) Zp += __shfl_xor_sync(~0u, Zp, o);
            float iz = 1.0f / Zp;
            // sweep 3: normalize + store only live windows
            if (ap) {
                unsigned lv = live;
                while (lv) {
                    int i = __ffs(lv) - 1;
                    lv &= lv - 1;
                    int idx = i * 32 + lane;
                    float4 p = row4[idx];
                    __stcs(&ap[idx],
                           make_float4(p.x * iz, p.y * iz, p.z * iz, p.w * iz));
                }
            }
            // y accumulation
            int cnt = s.cnt[r];
            if (cnt <= CAP) {
                for (int i = 0; i < cnt; i++) {
                    float a = s.pv[r][i] * iz;
                    int k = s.kv[r][i];
                    y0 += a * zb[(size_t)k * ZD + lane];
                    y1 += a * zb[(size_t)k * ZD + lane + 32];
                }
            } else {
                unsigned lv = live;
                while (lv) {
                    int i = __ffs(lv) - 1;
                    lv &= lv - 1;
                    for (int k = i * 128; k < i * 128 + 128; k++) {
                        float p = s.sc[r][k];
                        if (p != 0.f) {
                            float a = p * iz;
                            y0 += a * zb[(size_t)k * ZD + lane];
                            y1 += a * zb[(size_t)k * ZD + lane + 32];
                        }
                    }
                }
            }
        }
        s.yT[lane][r] = y0;
        s.yT[lane + 32][r] = y1;
    }
    cp_wait0();
    __syncthreads();

    // ---- output epilogue: packed f32x2, wv from smem ----
    if (outp) {
        int h = t & 255, qh = t >> 8;
        float ve = g_venc[b][h];
        ull ved = dup2(ve);
        ull acc[4];
#pragma unroll
        for (int j = 0; j < 4; j++) acc[j] = ved;
#pragma unroll 8
        for (int e = 0; e < ZD; e++) {
            float wvv = wvs[e * HD + h];
            ull wd = dup2(wvv);
            const ulonglong2* yr = ((const ulonglong2*)&s.yT[e][0]) + qh * 2;
            ulonglong2 ya = yr[0], yb2 = yr[1];
            fma2(acc[0], wd, ya.x);  fma2(acc[1], wd, ya.y);
            fma2(acc[2], wd, yb2.x); fma2(acc[3], wd, yb2.y);
        }
#pragma unroll
        for (int j = 0; j < 4; j++) {
            float lo, hi;
            unpack2(lo, hi, acc[j]);
            outp[((size_t)b * SL + q0 + qh * 8 + 2 * j + 0) * HD + h] = lo;
            outp[((size_t)b * SL + q0 + qh * 8 + 2 * j + 1) * HD + h] = hi;
        }
    }
}

// ============================== launch =====================================
extern "C" void kernel_launch(void* const* d_in, const int* in_sizes, int n_in,
                              void* d_out, int out_size) {
    const float* ehs  = (const float*)d_in[0];
    // d_in[1] = decoder_hidden_state (unused by reference)
    const float* z    = (const float*)d_in[2];
    const int*   mask = (const int*)d_in[3];
    const float* wq   = (const float*)d_in[4];
    const float* wk   = (const float*)d_in[5];
    const float* wv   = (const float*)d_in[6];

    const long OUT_N = (long)BB * SL * HD;   //  4,194,304
    const long ATT_N = (long)BB * SL * SL;   // 33,554,432
    float* o = (float*)d_out;
    float* outp = nullptr;
    float* attnp = nullptr;
    if ((long)out_size >= OUT_N + ATT_N) { outp = o; attnp = o + OUT_N; }
    else if ((long)out_size == ATT_N)    { attnp = o; }
    else                                 { outp = o; }

    const int PREP_SMEM = (ZD + 16) * KZP * 4;   // 83200 B (M part dominates)

    static int attr_set = 0;
    if (!attr_set) {
        cudaFuncSetAttribute(k_attn, cudaFuncAttributeMaxDynamicSharedMemorySize,
                             (int)sizeof(AttnSmem));
        cudaFuncSetAttribute(k_prep, cudaFuncAttributeMaxDynamicSharedMemorySize,
                             PREP_SMEM);
        attr_set = 1;
    }

    k_prep<<<BB + 4, 1024, PREP_SMEM>>>(ehs, z, wq, wk, wv);
    k_wc<<<128, 256>>>(z, wk);
    k_attn<<<BB * (SL / QT), 512, sizeof(AttnSmem)>>>(z, wv, mask, outp, attnp);
}